// round 3
// baseline (speedup 1.0000x reference)
#include <cuda_runtime.h>
#include <cuda_fp16.h>
#include <cstdint>
#include <cstddef>

// PSA3D permuted-window attention
// B=512 windows, N=512 q tokens, P=64 kv tokens, C=192, 6 heads x 32
// launches: bias_prep -> qkv gemm -> attention -> proj gemm

#define F_SCALE 0.17677669529663687f  // 32^-0.5

// scratch (device globals: allocation-free rule)
__device__ float g_q   [512u * 512u * 192u];  // (B,N,192) pre-scaled q
__device__ float g_kv  [512u * 512u * 48u];   // (B,N,48)  kv projection
__device__ float g_att [512u * 512u * 192u];  // (B,N,192) attention out
__device__ float g_bias[6u * 512u * 64u];     // (h,N,P)   gathered bias

__device__ __forceinline__ void mma16(float* d, const uint32_t* a, const uint32_t* b) {
    asm volatile(
        "mma.sync.aligned.m16n8k16.row.col.f32.f16.f16.f32 "
        "{%0,%1,%2,%3}, {%4,%5,%6,%7}, {%8,%9}, {%0,%1,%2,%3};"
        : "+f"(d[0]), "+f"(d[1]), "+f"(d[2]), "+f"(d[3])
        : "r"(a[0]), "r"(a[1]), "r"(a[2]), "r"(a[3]), "r"(b[0]), "r"(b[1]));
}

// ---------------------------------------------------------------------------
// bias_prep: g_bias[h][n][p] = bias_table[rpi[n*64+p]*6 + h]
// ---------------------------------------------------------------------------
__global__ void bias_prep_kernel(const float* __restrict__ bt, const int* __restrict__ rpi)
{
    int i = blockIdx.x * 256 + threadIdx.x;        // [0, 32768) = (n,p)
    int idx = rpi[i];
    #pragma unroll
    for (int h = 0; h < 6; ++h)
        g_bias[h * 32768 + i] = bt[idx * 6 + h];
}

// ---------------------------------------------------------------------------
// GEMM: (M x 192) @ (192 x BN).  BM=64, 256 threads, 8 warps = 4 row x 2 col.
// Warp tile: 16 rows x BN/2 cols.  fp16 mma m16n8k16, fp32 accumulate.
// IS_QKV: W = [wq | wkv]; cols <192 -> scaled q (out0), >=192 -> kv (out1).
// ---------------------------------------------------------------------------
template <int BN, bool IS_QKV>
__global__ __launch_bounds__(256, 2)
void gemm_kernel(const float* __restrict__ A,
                 const float* __restrict__ W0, const float* __restrict__ Bi0,
                 const float* __restrict__ W1, const float* __restrict__ Bi1,
                 float* __restrict__ out0, float* __restrict__ out1)
{
    constexpr int PA  = 200;        // A smem pitch (halves)
    constexpr int PB  = 24;         // B smem pitch (halves)
    constexpr int NT  = BN / 16;    // n-tiles per warp
    constexpr int NLD = BN / 16;    // B global loads per thread per chunk

    extern __shared__ __half sh[];
    __half* As = sh;                 // [64][PA]
    __half* Bs = sh + 64 * PA;       // [2][BN][PB]

    const int tid  = threadIdx.x;
    const int w    = tid >> 5, lane = tid & 31;
    const int g    = lane >> 2, t = lane & 3;
    const int wr   = w >> 1, wc = w & 1;
    const long row0 = (long)blockIdx.x * 64;

    // stage A (64 x 192 fp32 -> half)
    #pragma unroll
    for (int it = 0; it < 12; ++it) {
        int i  = it * 256 + tid;               // float4 slot, 3072 total
        int r  = i / 48, c4 = i % 48;
        float4 v = *(const float4*)(A + (row0 + r) * 192 + c4 * 4);
        __half* dst = As + r * PA + c4 * 4;
        dst[0] = __float2half_rn(v.x); dst[1] = __float2half_rn(v.y);
        dst[2] = __float2half_rn(v.z); dst[3] = __float2half_rn(v.w);
    }
    // stage B chunk 0 (k = 0..15)
    #pragma unroll
    for (int it = 0; it < NLD; ++it) {
        int i = it * 256 + tid;
        int kc = i / BN, n = i % BN;
        float v;
        if (IS_QKV) v = (n < 192) ? W0[kc * 192 + n] : W1[kc * 48 + n - 192];
        else        v = W0[kc * 192 + n];
        Bs[n * PB + kc] = __float2half_rn(v);
    }
    __syncthreads();

    float acc[NT][4];
    #pragma unroll
    for (int nt = 0; nt < NT; ++nt) {
        acc[nt][0] = 0.f; acc[nt][1] = 0.f; acc[nt][2] = 0.f; acc[nt][3] = 0.f;
    }

    float tmp[NLD];
    for (int ch = 0; ch < 12; ++ch) {
        // prefetch next W chunk into registers
        if (ch < 11) {
            int k0 = (ch + 1) * 16;
            #pragma unroll
            for (int it = 0; it < NLD; ++it) {
                int i = it * 256 + tid;
                int kc = i / BN, n = i % BN;
                if (IS_QKV) tmp[it] = (n < 192) ? W0[(k0 + kc) * 192 + n]
                                                : W1[(k0 + kc) * 48 + n - 192];
                else        tmp[it] = W0[(k0 + kc) * 192 + n];
            }
        }

        const __half* Bc = Bs + (ch & 1) * BN * PB;
        const __half* Ar = As + (wr * 16 + g) * PA + ch * 16 + t * 2;
        uint32_t a[4];
        a[0] = *(const uint32_t*)(Ar);
        a[1] = *(const uint32_t*)(Ar + 8 * PA);
        a[2] = *(const uint32_t*)(Ar + 8);
        a[3] = *(const uint32_t*)(Ar + 8 * PA + 8);
        #pragma unroll
        for (int nt = 0; nt < NT; ++nt) {
            const __half* Br = Bc + (wc * (BN / 2) + nt * 8 + g) * PB + t * 2;
            uint32_t b[2] = { *(const uint32_t*)Br, *(const uint32_t*)(Br + 8) };
            mma16(acc[nt], a, b);
        }

        if (ch < 11) {
            __half* Bn = Bs + ((ch + 1) & 1) * BN * PB;
            #pragma unroll
            for (int it = 0; it < NLD; ++it) {
                int i = it * 256 + tid;
                int kc = i / BN, n = i % BN;
                Bn[n * PB + kc] = __float2half_rn(tmp[it]);
            }
            __syncthreads();
        }
    }

    // epilogue
    const long r0 = row0 + wr * 16 + g, r1 = r0 + 8;
    #pragma unroll
    for (int nt = 0; nt < NT; ++nt) {
        int col = wc * (BN / 2) + nt * 8 + t * 2;
        if (IS_QKV) {
            if (col < 192) {
                float b0v = Bi0[col], b1v = Bi0[col + 1];
                float2 v0 = { (acc[nt][0] + b0v) * F_SCALE, (acc[nt][1] + b1v) * F_SCALE };
                float2 v1 = { (acc[nt][2] + b0v) * F_SCALE, (acc[nt][3] + b1v) * F_SCALE };
                *(float2*)(out0 + r0 * 192 + col) = v0;
                *(float2*)(out0 + r1 * 192 + col) = v1;
            } else {
                int c = col - 192;
                float b0v = Bi1[c], b1v = Bi1[c + 1];
                float2 v0 = { acc[nt][0] + b0v, acc[nt][1] + b1v };
                float2 v1 = { acc[nt][2] + b0v, acc[nt][3] + b1v };
                *(float2*)(out1 + r0 * 48 + c) = v0;
                *(float2*)(out1 + r1 * 48 + c) = v1;
            }
        } else {
            float b0v = Bi0[col], b1v = Bi0[col + 1];
            float2 v0 = { acc[nt][0] + b0v, acc[nt][1] + b1v };
            float2 v1 = { acc[nt][2] + b0v, acc[nt][3] + b1v };
            *(float2*)(out0 + r0 * 192 + col) = v0;
            *(float2*)(out0 + r1 * 192 + col) = v1;
        }
    }
}

// ---------------------------------------------------------------------------
// Attention: one block per (window b, head h), 256 threads = 8 warps.
// Warp handles 64 q rows as 4 m-tiles of 16.
// ---------------------------------------------------------------------------
__global__ __launch_bounds__(256)
void attn_kernel()
{
    __shared__ __half Ks[64 * 40];        // K as [p][d]
    __shared__ __half Vs[32 * 72];        // V as [d][p]
    __shared__ __half Ps[8 * 16 * 72];    // per-warp q / P staging

    const int tid = threadIdx.x, w = tid >> 5, lane = tid & 31;
    const int g = lane >> 2, t = lane & 3;
    const int b = blockIdx.x, h = blockIdx.y;

    // gather K/V: channel-folded 2x2x2 spatial groups
    const float* kvb = g_kv + (size_t)b * 512 * 48;
    #pragma unroll
    for (int it = 0; it < 8; ++it) {
        int i = it * 256 + tid;           // [0, 2048) = (p,d)
        int p = i >> 5, d = i & 31;
        int pd = p >> 4, ph = (p >> 2) & 3, pw = p & 3;
        int ik = h * 32 + d;              // K folded-channel index (m < 192)
        int fk = ik / 48, ck = ik % 48;
        int iv = ik + 192;                // V folded-channel index
        int fv = iv / 48, cv = iv % 48;
        int nk = (pd * 2 + ((fk >> 2) & 1)) * 64 + (ph * 2 + ((fk >> 1) & 1)) * 8
               + pw * 2 + (fk & 1);
        int nv = (pd * 2 + ((fv >> 2) & 1)) * 64 + (ph * 2 + ((fv >> 1) & 1)) * 8
               + pw * 2 + (fv & 1);
        Ks[p * 40 + d] = __float2half_rn(kvb[nk * 48 + ck]);
        Vs[d * 72 + p] = __float2half_rn(kvb[nv * 48 + cv]);
    }
    __syncthreads();

    __half* Qs = Ps + w * 16 * 72;
    const float* qb = g_q   + (size_t)b * 512 * 192 + h * 32;
    float*       ob = g_att + (size_t)b * 512 * 192 + h * 32;
    const float* bm = g_bias + h * 32768;

    for (int mt = 0; mt < 4; ++mt) {
        const int mrow = w * 64 + mt * 16;

        // stage q tile 16x32 -> half
        #pragma unroll
        for (int j = 0; j < 4; ++j) {
            int fi = j * 32 + lane;       // [0,128): 8 float4 per row
            int r = fi >> 3, c4 = fi & 7;
            float4 v = *(const float4*)(qb + (size_t)(mrow + r) * 192 + c4 * 4);
            __half* dst = Qs + r * 72 + c4 * 4;
            dst[0] = __float2half_rn(v.x); dst[1] = __float2half_rn(v.y);
            dst[2] = __float2half_rn(v.z); dst[3] = __float2half_rn(v.w);
        }
        __syncwarp();

        // scores = q @ K^T : 8 n-tiles over P=64, 2 k-chunks over d=32
        float s[8][4];
        #pragma unroll
        for (int nt = 0; nt < 8; ++nt) { s[nt][0]=0.f; s[nt][1]=0.f; s[nt][2]=0.f; s[nt][3]=0.f; }
        #pragma unroll
        for (int ks = 0; ks < 2; ++ks) {
            const __half* Ar = Qs + g * 72 + ks * 16 + t * 2;
            uint32_t a[4];
            a[0] = *(const uint32_t*)(Ar);
            a[1] = *(const uint32_t*)(Ar + 8 * 72);
            a[2] = *(const uint32_t*)(Ar + 8);
            a[3] = *(const uint32_t*)(Ar + 8 * 72 + 8);
            #pragma unroll
            for (int nt = 0; nt < 8; ++nt) {
                const __half* Br = Ks + (nt * 8 + g) * 40 + ks * 16 + t * 2;
                uint32_t bb[2] = { *(const uint32_t*)Br, *(const uint32_t*)(Br + 8) };
                mma16(s[nt], a, bb);
            }
        }

        // bias add + row softmax (rows r0, r1; each row spread over 4 lanes)
        const int r0 = mrow + g, r1 = r0 + 8;
        float m0 = -1e30f, m1 = -1e30f;
        #pragma unroll
        for (int nt = 0; nt < 8; ++nt) {
            float2 b0v = *(const float2*)(bm + r0 * 64 + nt * 8 + t * 2);
            float2 b1v = *(const float2*)(bm + r1 * 64 + nt * 8 + t * 2);
            s[nt][0] += b0v.x; s[nt][1] += b0v.y;
            s[nt][2] += b1v.x; s[nt][3] += b1v.y;
            m0 = fmaxf(m0, fmaxf(s[nt][0], s[nt][1]));
            m1 = fmaxf(m1, fmaxf(s[nt][2], s[nt][3]));
        }
        m0 = fmaxf(m0, __shfl_xor_sync(0xffffffffu, m0, 1));
        m0 = fmaxf(m0, __shfl_xor_sync(0xffffffffu, m0, 2));
        m1 = fmaxf(m1, __shfl_xor_sync(0xffffffffu, m1, 1));
        m1 = fmaxf(m1, __shfl_xor_sync(0xffffffffu, m1, 2));
        float sum0 = 0.f, sum1 = 0.f;
        #pragma unroll
        for (int nt = 0; nt < 8; ++nt) {
            s[nt][0] = __expf(s[nt][0] - m0); sum0 += s[nt][0];
            s[nt][1] = __expf(s[nt][1] - m0); sum0 += s[nt][1];
            s[nt][2] = __expf(s[nt][2] - m1); sum1 += s[nt][2];
            s[nt][3] = __expf(s[nt][3] - m1); sum1 += s[nt][3];
        }
        sum0 += __shfl_xor_sync(0xffffffffu, sum0, 1);
        sum0 += __shfl_xor_sync(0xffffffffu, sum0, 2);
        sum1 += __shfl_xor_sync(0xffffffffu, sum1, 1);
        sum1 += __shfl_xor_sync(0xffffffffu, sum1, 2);
        const float inv0 = 1.f / sum0, inv1 = 1.f / sum1;

        // restage P (C layout) -> smem -> A-fragment layout
        __syncwarp();
        #pragma unroll
        for (int nt = 0; nt < 8; ++nt) {
            *(__half2*)(Qs + g * 72 + nt * 8 + t * 2) =
                __floats2half2_rn(s[nt][0] * inv0, s[nt][1] * inv0);
            *(__half2*)(Qs + (g + 8) * 72 + nt * 8 + t * 2) =
                __floats2half2_rn(s[nt][2] * inv1, s[nt][3] * inv1);
        }
        __syncwarp();

        // out = P @ V : 4 n-tiles over d=32, 4 k-chunks over P=64
        float o[4][4];
        #pragma unroll
        for (int nt = 0; nt < 4; ++nt) { o[nt][0]=0.f; o[nt][1]=0.f; o[nt][2]=0.f; o[nt][3]=0.f; }
        #pragma unroll
        for (int ks = 0; ks < 4; ++ks) {
            const __half* Ar = Qs + g * 72 + ks * 16 + t * 2;
            uint32_t a[4];
            a[0] = *(const uint32_t*)(Ar);
            a[1] = *(const uint32_t*)(Ar + 8 * 72);
            a[2] = *(const uint32_t*)(Ar + 8);
            a[3] = *(const uint32_t*)(Ar + 8 * 72 + 8);
            #pragma unroll
            for (int nt = 0; nt < 4; ++nt) {
                const __half* Br = Vs + (nt * 8 + g) * 72 + ks * 16 + t * 2;
                uint32_t bb[2] = { *(const uint32_t*)Br, *(const uint32_t*)(Br + 8) };
                mma16(o[nt], a, bb);
            }
        }

        #pragma unroll
        for (int nt = 0; nt < 4; ++nt) {
            int col = nt * 8 + t * 2;
            float2 v0 = { o[nt][0], o[nt][1] };
            float2 v1 = { o[nt][2], o[nt][3] };
            *(float2*)(ob + (size_t)r0 * 192 + col) = v0;
            *(float2*)(ob + (size_t)r1 * 192 + col) = v1;
        }
        __syncwarp();
    }
}

// ---------------------------------------------------------------------------
extern "C" void kernel_launch(void* const* d_in, const int* in_sizes, int n_in,
                              void* d_out, int out_size)
{
    const float* x     = (const float*)d_in[0];
    const float* wq    = (const float*)d_in[1];
    const float* bq    = (const float*)d_in[2];
    const float* wkv   = (const float*)d_in[3];
    const float* bkv   = (const float*)d_in[4];
    const float* btab  = (const float*)d_in[5];
    const float* wproj = (const float*)d_in[6];
    const float* bproj = (const float*)d_in[7];
    const int*   rpi   = (const int*)d_in[8];
    float* out = (float*)d_out;

    float *qp, *kvp, *attp;
    cudaGetSymbolAddress((void**)&qp,   g_q);
    cudaGetSymbolAddress((void**)&kvp,  g_kv);
    cudaGetSymbolAddress((void**)&attp, g_att);

    const int S_QKV  = (64 * 200 + 2 * 240 * 24) * 2;  // 48640 B
    const int S_PROJ = (64 * 200 + 2 * 192 * 24) * 2;  // 44032 B
    cudaFuncSetAttribute(gemm_kernel<240, true>,
                         cudaFuncAttributeMaxDynamicSharedMemorySize, S_QKV);
    cudaFuncSetAttribute(gemm_kernel<192, false>,
                         cudaFuncAttributeMaxDynamicSharedMemorySize, S_PROJ);

    bias_prep_kernel<<<128, 256>>>(btab, rpi);
    gemm_kernel<240, true><<<4096, 256, S_QKV>>>(x, wq, bq, wkv, bkv, qp, kvp);
    attn_kernel<<<dim3(512, 6), 256>>>();
    gemm_kernel<192, false><<<4096, 256, S_PROJ>>>(attp, wproj, bproj,
                                                   nullptr, nullptr, out, nullptr);
}

// round 5
// speedup vs baseline: 1.6291x; 1.6291x over previous
#include <cuda_runtime.h>
#include <cuda_fp16.h>
#include <cstdint>
#include <cstddef>

// PSA3D permuted-window attention
// B=512 windows, N=512 q tokens, P=64 kv tokens, C=192, 6 heads x 32
// launches: bias_prep -> qkv gemm -> attention -> proj gemm
// GEMMs: fp16 mma m16n8k16, ldmatrix fragments, full-K smem staging.
// Intermediates stored as half (only ever consumed as fp16 mma operands).

#define F_SCALE 0.17677669529663687f  // 32^-0.5

// scratch (device globals: allocation-free rule)
__device__ __half g_q   [512u * 512u * 192u];  // (B,N,192) pre-scaled q
__device__ __half g_kv  [512u * 512u * 48u];   // (B,N,48)  kv projection
__device__ __half g_att [512u * 512u * 192u];  // (B,N,192) attention out
__device__ float  g_bias[6u * 512u * 64u];     // (h,N,P)   gathered bias

__device__ __forceinline__ uint32_t s2u(const void* p) {
    return (uint32_t)__cvta_generic_to_shared(p);
}
__device__ __forceinline__ uint32_t packh2(float x, float y) {
    __half2 h = __floats2half2_rn(x, y);
    return *(uint32_t*)&h;
}
__device__ __forceinline__ void mma16(float* d, const uint32_t* a, const uint32_t* b) {
    asm volatile(
        "mma.sync.aligned.m16n8k16.row.col.f32.f16.f16.f32 "
        "{%0,%1,%2,%3}, {%4,%5,%6,%7}, {%8,%9}, {%0,%1,%2,%3};"
        : "+f"(d[0]), "+f"(d[1]), "+f"(d[2]), "+f"(d[3])
        : "r"(a[0]), "r"(a[1]), "r"(a[2]), "r"(a[3]), "r"(b[0]), "r"(b[1]));
}
__device__ __forceinline__ void ldsm4(uint32_t* d, uint32_t a) {
    asm volatile("ldmatrix.sync.aligned.m8n8.x4.shared.b16 {%0,%1,%2,%3}, [%4];"
        : "=r"(d[0]), "=r"(d[1]), "=r"(d[2]), "=r"(d[3]) : "r"(a));
}
__device__ __forceinline__ void ldsm4t(uint32_t* d, uint32_t a) {
    asm volatile("ldmatrix.sync.aligned.m8n8.x4.trans.shared.b16 {%0,%1,%2,%3}, [%4];"
        : "=r"(d[0]), "=r"(d[1]), "=r"(d[2]), "=r"(d[3]) : "r"(a));
}

// ---------------------------------------------------------------------------
// bias_prep: g_bias[h][n][p] = bias_table[rpi[n*64+p]*6 + h]
// ---------------------------------------------------------------------------
__global__ void bias_prep_kernel(const float* __restrict__ bt, const int* __restrict__ rpi)
{
    int i = blockIdx.x * 256 + threadIdx.x;        // [0, 32768) = (n,p)
    int idx = rpi[i];
    #pragma unroll
    for (int h = 0; h < 6; ++h)
        g_bias[h * 32768 + i] = bt[idx * 6 + h];
}

// ---------------------------------------------------------------------------
// GEMM: (M x 192) @ (192 x BN). BM=128, 256 threads, warps 4x2.
// Full K staged once; fragments via ldmatrix. Warp tile 32 x BN/2.
// IS_QKV: A fp32 (x), W=[wq|wkv]; cols<192 -> scaled-q half, else kv half.
// else:    A half (g_att), out fp32 (d_out).
// ---------------------------------------------------------------------------
template <int BN, bool IS_QKV>
__global__ __launch_bounds__(256, 1)
void gemm_kernel(const void* __restrict__ Ain,
                 const float* __restrict__ W0, const float* __restrict__ Bi0,
                 const float* __restrict__ W1, const float* __restrict__ Bi1,
                 void* __restrict__ out0, void* __restrict__ out1)
{
    constexpr int PA  = 200;          // A smem pitch (halves): 400B ≡ 16 mod 128
    constexpr int PBN = BN + 8;       // B smem pitch (halves)
    constexpr int HN  = BN / 2;       // cols per warp
    constexpr int NT  = HN / 8;       // n8-tiles per warp (12 or 15)
    constexpr int NTP = (NT + 1) / 2; // ldmatrix pairs (phantom tile discarded)

    extern __shared__ __half sh[];
    __half* As = sh;                  // [128][PA]
    __half* Bs = sh + 128 * PA;       // [192][PBN]  (k-major)

    const int tid = threadIdx.x, w = tid >> 5, lane = tid & 31;
    const int g = lane >> 2, t = lane & 3;
    const int wr = w >> 1, wc = w & 1;
    const int lane7 = lane & 7, quad = lane >> 3;
    const long row0 = (long)blockIdx.x * 128;

    // ---- stage A (128 x 192 -> half, pitch PA) ----
    if (IS_QKV) {
        const float* A = (const float*)Ain;
        #pragma unroll
        for (int it = 0; it < 24; ++it) {
            int i = it * 256 + tid, r = i / 48, c4 = i % 48;
            float4 v = *(const float4*)(A + (row0 + r) * 192 + c4 * 4);
            uint2 pk = { packh2(v.x, v.y), packh2(v.z, v.w) };
            *(uint2*)(As + r * PA + c4 * 4) = pk;
        }
    } else {
        const __half* A = (const __half*)Ain;
        #pragma unroll
        for (int it = 0; it < 12; ++it) {
            int i = it * 256 + tid, r = i / 24, c8 = i % 24;
            uint4 v = *(const uint4*)(A + (row0 + r) * 192 + c8 * 8);
            *(uint4*)(As + r * PA + c8 * 8) = v;
        }
    }
    // ---- stage B: W0 (192x192) [+ W1 (192x48) at col 192] ----
    #pragma unroll
    for (int it = 0; it < 36; ++it) {
        int i = it * 256 + tid, r = i / 48, c4 = i % 48;
        float4 v = *(const float4*)(W0 + r * 192 + c4 * 4);
        uint2 pk = { packh2(v.x, v.y), packh2(v.z, v.w) };
        *(uint2*)(Bs + r * PBN + c4 * 4) = pk;
    }
    if (IS_QKV) {
        #pragma unroll
        for (int it = 0; it < 9; ++it) {
            int i = it * 256 + tid, r = i / 12, c4 = i % 12;
            float4 v = *(const float4*)(W1 + r * 48 + c4 * 4);
            uint2 pk = { packh2(v.x, v.y), packh2(v.z, v.w) };
            *(uint2*)(Bs + r * PBN + 192 + c4 * 4) = pk;
        }
    }
    __syncthreads();

    float acc[2][NT][4] = {};

    // ldmatrix base addresses
    uint32_t aB[2], bB[NTP];
    #pragma unroll
    for (int mi = 0; mi < 2; ++mi)
        aB[mi] = s2u(As + (wr * 32 + mi * 16 + lane7 + (quad & 1) * 8) * PA
                        + (quad >> 1) * 8);
    #pragma unroll
    for (int pr = 0; pr < NTP; ++pr)
        bB[pr] = s2u(Bs + ((quad & 1) * 8 + lane7) * PBN
                        + wc * HN + pr * 16 + (quad >> 1) * 8);

    #pragma unroll
    for (int ch = 0; ch < 12; ++ch) {
        uint32_t a[2][4];
        ldsm4(a[0], aB[0] + ch * 32);
        ldsm4(a[1], aB[1] + ch * 32);
        #pragma unroll
        for (int pr = 0; pr < NTP; ++pr) {
            uint32_t b[4];
            ldsm4t(b, bB[pr] + ch * (16 * PBN * 2));
            #pragma unroll
            for (int mi = 0; mi < 2; ++mi) {
                mma16(acc[mi][2 * pr], a[mi], b);
                if (2 * pr + 1 < NT) mma16(acc[mi][2 * pr + 1], a[mi], b + 2);
            }
        }
    }

    // ---- epilogue ----
    #pragma unroll
    for (int mi = 0; mi < 2; ++mi) {
        const long r0 = row0 + wr * 32 + mi * 16 + g;
        #pragma unroll
        for (int nt = 0; nt < NT; ++nt) {
            int col = wc * HN + nt * 8 + t * 2;
            const float* ac = acc[mi][nt];
            if (IS_QKV) {
                if (col < 192) {
                    float b0 = Bi0[col], b1 = Bi0[col + 1];
                    __half* o = (__half*)out0;
                    *(uint32_t*)(o + r0 * 192 + col) =
                        packh2((ac[0] + b0) * F_SCALE, (ac[1] + b1) * F_SCALE);
                    *(uint32_t*)(o + (r0 + 8) * 192 + col) =
                        packh2((ac[2] + b0) * F_SCALE, (ac[3] + b1) * F_SCALE);
                } else {
                    int c = col - 192;
                    float b0 = Bi1[c], b1 = Bi1[c + 1];
                    __half* o = (__half*)out1;
                    *(uint32_t*)(o + r0 * 48 + c)       = packh2(ac[0] + b0, ac[1] + b1);
                    *(uint32_t*)(o + (r0 + 8) * 48 + c) = packh2(ac[2] + b0, ac[3] + b1);
                }
            } else {
                float b0 = Bi0[col], b1 = Bi0[col + 1];
                float* o = (float*)out0;
                *(float2*)(o + r0 * 192 + col)       = make_float2(ac[0] + b0, ac[1] + b1);
                *(float2*)(o + (r0 + 8) * 192 + col) = make_float2(ac[2] + b0, ac[3] + b1);
            }
        }
    }
}

// ---------------------------------------------------------------------------
// Attention: block per (window b, head h), 256 threads = 8 warps.
// Warp: 64 q rows as 4 m16 tiles. Fragments via ldmatrix; P passes from
// score C-regs directly into PV A-regs (no smem restage).
// ---------------------------------------------------------------------------
__global__ __launch_bounds__(256)
void attn_kernel()
{
    __shared__ __align__(16) __half Ks[64 * 40];     // [p][d]
    __shared__ __align__(16) __half Vs[32 * 72];     // [d][p]
    __shared__ __align__(16) __half Qs[8 * 16 * 40]; // per-warp q tile

    const int tid = threadIdx.x, w = tid >> 5, lane = tid & 31;
    const int g = lane >> 2, t = lane & 3;
    const int lane7 = lane & 7, quad = lane >> 3;
    const int b = blockIdx.x, h = blockIdx.y;

    // gather K/V: channel-folded 2x2x2 spatial groups
    const __half* kvb = g_kv + (size_t)b * 512 * 48;
    #pragma unroll
    for (int it = 0; it < 8; ++it) {
        int i = it * 256 + tid;               // (p,d)
        int p = i >> 5, d = i & 31;
        int pd = p >> 4, ph = (p >> 2) & 3, pw = p & 3;
        int ik = h * 32 + d, fk = ik / 48, ck = ik % 48;
        int iv = ik + 192,   fv = iv / 48, cv = iv % 48;
        int nk = (pd * 2 + ((fk >> 2) & 1)) * 64 + (ph * 2 + ((fk >> 1) & 1)) * 8
               + pw * 2 + (fk & 1);
        int nv = (pd * 2 + ((fv >> 2) & 1)) * 64 + (ph * 2 + ((fv >> 1) & 1)) * 8
               + pw * 2 + (fv & 1);
        Ks[p * 40 + d] = kvb[nk * 48 + ck];
        Vs[d * 72 + p] = kvb[nv * 48 + cv];
    }
    __syncthreads();

    __half* Qw = Qs + w * 640;
    const __half* qb = g_q   + (size_t)b * 512 * 192 + h * 32;
    __half*       ob = g_att + (size_t)b * 512 * 192 + h * 32;
    const float*  bm = g_bias + h * 32768;

    const uint32_t aAddr = s2u(Qw + (lane7 + (quad & 1) * 8) * 40 + (quad >> 1) * 8);
    uint32_t kAddr[4], vAddr[2];
    #pragma unroll
    for (int p4 = 0; p4 < 4; ++p4)
        kAddr[p4] = s2u(Ks + (p4 * 16 + (quad >> 1) * 8 + lane7) * 40 + (quad & 1) * 8);
    #pragma unroll
    for (int d4 = 0; d4 < 2; ++d4)
        vAddr[d4] = s2u(Vs + (d4 * 16 + (quad >> 1) * 8 + lane7) * 72 + (quad & 1) * 8);

    for (int mt = 0; mt < 4; ++mt) {
        const int mrow = w * 64 + mt * 16;

        // stage q tile 16x32 (half, uint4)
        #pragma unroll
        for (int j = 0; j < 2; ++j) {
            int fi = j * 32 + lane, r = fi >> 2, c8 = fi & 3;
            uint4 v = *(const uint4*)(qb + (size_t)(mrow + r) * 192 + c8 * 8);
            *(uint4*)(Qw + r * 40 + c8 * 8) = v;
        }
        __syncwarp();

        uint32_t a[2][4];
        ldsm4(a[0], aAddr);
        ldsm4(a[1], aAddr + 32);

        // scores = q @ K^T
        float s[8][4] = {};
        #pragma unroll
        for (int ks = 0; ks < 2; ++ks)
            #pragma unroll
            for (int p4 = 0; p4 < 4; ++p4) {
                uint32_t bb[4];
                ldsm4(bb, kAddr[p4] + ks * 32);
                mma16(s[2 * p4],     a[ks], bb);
                mma16(s[2 * p4 + 1], a[ks], bb + 2);
            }

        // bias + row softmax (rows r0, r0+8; each row across 4 lanes)
        const int r0 = mrow + g, r1 = r0 + 8;
        float m0 = -1e30f, m1 = -1e30f;
        #pragma unroll
        for (int nt = 0; nt < 8; ++nt) {
            float2 b0v = *(const float2*)(bm + r0 * 64 + nt * 8 + t * 2);
            float2 b1v = *(const float2*)(bm + r1 * 64 + nt * 8 + t * 2);
            s[nt][0] += b0v.x; s[nt][1] += b0v.y;
            s[nt][2] += b1v.x; s[nt][3] += b1v.y;
            m0 = fmaxf(m0, fmaxf(s[nt][0], s[nt][1]));
            m1 = fmaxf(m1, fmaxf(s[nt][2], s[nt][3]));
        }
        m0 = fmaxf(m0, __shfl_xor_sync(0xffffffffu, m0, 1));
        m0 = fmaxf(m0, __shfl_xor_sync(0xffffffffu, m0, 2));
        m1 = fmaxf(m1, __shfl_xor_sync(0xffffffffu, m1, 1));
        m1 = fmaxf(m1, __shfl_xor_sync(0xffffffffu, m1, 2));
        float sum0 = 0.f, sum1 = 0.f;
        #pragma unroll
        for (int nt = 0; nt < 8; ++nt) {
            s[nt][0] = __expf(s[nt][0] - m0); sum0 += s[nt][0];
            s[nt][1] = __expf(s[nt][1] - m0); sum0 += s[nt][1];
            s[nt][2] = __expf(s[nt][2] - m1); sum1 += s[nt][2];
            s[nt][3] = __expf(s[nt][3] - m1); sum1 += s[nt][3];
        }
        sum0 += __shfl_xor_sync(0xffffffffu, sum0, 1);
        sum0 += __shfl_xor_sync(0xffffffffu, sum0, 2);
        sum1 += __shfl_xor_sync(0xffffffffu, sum1, 1);
        sum1 += __shfl_xor_sync(0xffffffffu, sum1, 2);
        const float inv0 = 1.f / sum0, inv1 = 1.f / sum1;
        #pragma unroll
        for (int nt = 0; nt < 8; ++nt) {
            s[nt][0] *= inv0; s[nt][1] *= inv0;
            s[nt][2] *= inv1; s[nt][3] *= inv1;
        }

        // out = P @ V; A-fragments come straight from the score C-layout
        float o[4][4] = {};
        #pragma unroll
        for (int ks = 0; ks < 4; ++ks) {
            uint32_t pa[4];
            pa[0] = packh2(s[2 * ks][0],     s[2 * ks][1]);
            pa[1] = packh2(s[2 * ks][2],     s[2 * ks][3]);
            pa[2] = packh2(s[2 * ks + 1][0], s[2 * ks + 1][1]);
            pa[3] = packh2(s[2 * ks + 1][2], s[2 * ks + 1][3]);
            #pragma unroll
            for (int d4 = 0; d4 < 2; ++d4) {
                uint32_t bb[4];
                ldsm4(bb, vAddr[d4] + ks * 32);
                mma16(o[2 * d4],     pa, bb);
                mma16(o[2 * d4 + 1], pa, bb + 2);
            }
        }

        #pragma unroll
        for (int nt = 0; nt < 4; ++nt) {
            int col = nt * 8 + t * 2;
            *(uint32_t*)(ob + (size_t)r0 * 192 + col) = packh2(o[nt][0], o[nt][1]);
            *(uint32_t*)(ob + (size_t)r1 * 192 + col) = packh2(o[nt][2], o[nt][3]);
        }
        __syncwarp();
    }
}

// ---------------------------------------------------------------------------
extern "C" void kernel_launch(void* const* d_in, const int* in_sizes, int n_in,
                              void* d_out, int out_size)
{
    const float* x     = (const float*)d_in[0];
    const float* wq    = (const float*)d_in[1];
    const float* bq    = (const float*)d_in[2];
    const float* wkv   = (const float*)d_in[3];
    const float* bkv   = (const float*)d_in[4];
    const float* btab  = (const float*)d_in[5];
    const float* wproj = (const float*)d_in[6];
    const float* bproj = (const float*)d_in[7];
    const int*   rpi   = (const int*)d_in[8];
    float* out = (float*)d_out;

    void *qp, *kvp, *attp;
    cudaGetSymbolAddress(&qp,   g_q);
    cudaGetSymbolAddress(&kvp,  g_kv);
    cudaGetSymbolAddress(&attp, g_att);

    const int S_QKV  = (128 * 200 + 192 * 248) * 2;  // 146432 B
    const int S_PROJ = (128 * 200 + 192 * 200) * 2;  // 128000 B
    cudaFuncSetAttribute(gemm_kernel<240, true>,
                         cudaFuncAttributeMaxDynamicSharedMemorySize, S_QKV);
    cudaFuncSetAttribute(gemm_kernel<192, false>,
                         cudaFuncAttributeMaxDynamicSharedMemorySize, S_PROJ);

    bias_prep_kernel<<<128, 256>>>(btab, rpi);
    gemm_kernel<240, true><<<2048, 256, S_QKV>>>(x, wq, bq, wkv, bkv, qp, kvp);
    attn_kernel<<<dim3(512, 6), 256>>>();
    gemm_kernel<192, false><<<2048, 256, S_PROJ>>>(attp, wproj, bproj,
                                                   nullptr, nullptr, out, nullptr);
}